// round 17
// baseline (speedup 1.0000x reference)
#include <cuda_runtime.h>
#include <cstdint>

#define BATCH 2048
#define TLEN  4096
#define ALPHA_C 0.95f
#define THETA_C 0.05f

#define ROWS_PB 32
#define SEG     512
#define NSEG    (TLEN / SEG)     // 8
#define WU      384              // warm-up steps (alpha^384 ~ 3e-9)
#define TILE    32
#define TS      36               // smem row stride (floats)

#define CP_ASYNC16(dst, src) \
    asm volatile("cp.async.cg.shared.global [%0], [%1], 16;" :: "r"(dst), "l"(src))
#define CP_COMMIT() asm volatile("cp.async.commit_group;")

#define PACK2(out, lo, hi) \
    asm("mov.b64 %0, {%1, %2};" : "=l"(out) : "f"(lo), "f"(hi))
#define FMA2(d, a, b, c) \
    asm("fma.rn.f32x2 %0, %1, %2, %3;" : "=l"(d) : "l"(a), "l"(b), "l"(c))

__device__ __forceinline__ uint32_t smem_u32(const void* p) {
    return (uint32_t)__cvta_generic_to_shared(p);
}

// ---------------------------------------------------------------------------
// LIF + WTA step — decision logic IDENTICAL to validated rounds 1-16.
// ---------------------------------------------------------------------------
__device__ __forceinline__ void lif_step_s(float u0, float u1, float u2,
                                           float& v0, float& v1, float& v2,
                                           float& s0, float& s1, float& s2)
{
    float w0 = fmaf(ALPHA_C, v0, u0);
    float w1 = fmaf(ALPHA_C, v1, u1);
    float w2 = fmaf(ALPHA_C, v2, u2);
    float m0 = w0 - THETA_C;
    float m1 = w1 - THETA_C;
    float m2 = w2 - THETA_C;
    float best = fmaxf(m0, fmaxf(m1, m2));
    bool fire = (best >= 0.0f);
    bool t0 = (m0 == best);
    bool t1 = (m1 == best);
    bool e0 = fire && t0;
    bool e1 = fire && t1 && !t0;
    bool e2 = fire && !t0 && !t1;
    s0 = e0 ? 1.0f : 0.0f;
    s1 = e1 ? 1.0f : 0.0f;
    s2 = e2 ? 1.0f : 0.0f;
    v0 = e0 ? m0 : w0;
    v1 = e1 ? m1 : w1;
    v2 = e2 ? m2 : w2;
}

// ---------------------------------------------------------------------------
// Fused conv + LIF, warp-specialized pipeline.
// Block = 160 threads: warp 0 = LIF; warps 1-4 = conv octets 0-3 + all stores.
// Per iteration ti (ONE barrier):
//   warps1-4: stage x(ti+2) [cp.async ring, 4 slots, no halo re-read]
//   all: wait + __syncthreads
//   warp0:    LIF tile ti from ub[ti&1] -> spikes to sb[ti&1]
//   warps1-4: store u(ti) from ub[ti&1]; conv(ti+1) -> ub[(ti+1)&1];
//             store s(ti-1) from sb[(ti-1)&1]
// smem layout (dynamic, 74176 B):
//   wb[56] ull | xs[4][32][TS] | ub[2][3][32][TS] | sb[2][3][32][TS]
// ---------------------------------------------------------------------------
#define XS(slot, row, off) smx[(((slot) * 32 + (row)) * TS) + (off)]
#define UB(buf, k, row, off) smu[((((buf) * 3 + (k)) * 32 + (row)) * TS) + (off)]
#define SB(buf, k, row, off) sms[((((buf) * 3 + (k)) * 32 + (row)) * TS) + (off)]

__global__ void __launch_bounds__(160, 3) fused_kernel(
    const float* __restrict__ x,
    const float* __restrict__ w8,
    const float* __restrict__ w16,
    const float* __restrict__ w32,
    float* __restrict__ uo,
    float* __restrict__ so)
{
    extern __shared__ float sm[];
    unsigned long long* wb = reinterpret_cast<unsigned long long*>(sm);  // 56 ull
    float* smx = sm + 112;                 // 4*32*TS = 4608
    float* smu = smx + 4 * 32 * TS;        // 2*3*32*TS = 6912
    float* sms = smu + 2 * 3 * 32 * TS;    // 6912

    const int tid  = threadIdx.x;          // 0..159
    const int wid  = tid >> 5;
    const int lane = tid & 31;
    const int b0   = blockIdx.x * ROWS_PB;
    const int seg  = blockIdx.y;

    const int t_out0   = seg * SEG;
    const int t_begin  = (t_out0 >= WU) ? (t_out0 - WU) : 0;
    const int ntiles   = (t_out0 + SEG - t_begin) / TILE;   // 16 or 28
    const int wu_tiles = (t_out0 - t_begin) / TILE;         // 0 or 12

    if (tid < 56) {
        float w = (tid < 32) ? w32[tid] : (tid < 48 ? w16[tid - 32] : w8[tid - 48]);
        unsigned long long w2; PACK2(w2, w, w);
        wb[tid] = w2;
    }

    const int ct = tid - 32;               // conv-thread index 0..127 (wid>=1)
    const int tx = wid - 1;                // conv octet 0..3

    // ---- prologue: halo -> slot 3, tile0 -> slot 0 (group1); tile1 (group2)
    if (wid >= 1) {
#pragma unroll
        for (int i = 0; i < 2; i++) {
            int p = ct + (i << 7);
            int row = p >> 3, f4 = p & 7;
            if (t_begin == 0) {
                *reinterpret_cast<float4*>(&XS(3, row, f4 << 2)) =
                    make_float4(0.f, 0.f, 0.f, 0.f);
            } else {
                CP_ASYNC16(smem_u32(&XS(3, row, f4 << 2)),
                           x + (size_t)(b0 + row) * TLEN + t_begin - 32 + (f4 << 2));
            }
            CP_ASYNC16(smem_u32(&XS(0, row, f4 << 2)),
                       x + (size_t)(b0 + row) * TLEN + t_begin + (f4 << 2));
        }
        CP_COMMIT();
        if (ntiles > 1) {
#pragma unroll
            for (int i = 0; i < 2; i++) {
                int p = ct + (i << 7);
                int row = p >> 3, f4 = p & 7;
                CP_ASYNC16(smem_u32(&XS(1, row, f4 << 2)),
                           x + (size_t)(b0 + row) * TLEN + t_begin + TILE + (f4 << 2));
            }
            CP_COMMIT();
            asm volatile("cp.async.wait_group 1;");
        } else {
            asm volatile("cp.async.wait_group 0;");
        }
    }
    __syncthreads();

    // conv(tile T) by warps 1-4: window slots (T-1)&3 and T&3
#define CONV_TILE(T)                                                            \
    do {                                                                        \
        const int Ls = ((T) - 1) & 3, Rs = (T) & 3;                             \
        float4 q[10];                                                           \
        _Pragma("unroll")                                                       \
        for (int n = 0; n < 10; n++) {                                          \
            int off = (tx << 3) + (n << 2);                                     \
            const float* src = (off < 32) ? &XS(Ls, lane, off)                  \
                                          : &XS(Rs, lane, off - 32);            \
            q[n] = *reinterpret_cast<const float4*>(src);                       \
        }                                                                       \
        const float* qf = reinterpret_cast<const float*>(q);                    \
        unsigned long long xp[38];                                              \
        _Pragma("unroll")                                                       \
        for (int m = 0; m < 38; m++) PACK2(xp[m], qf[m + 1], qf[m + 2]);        \
        unsigned long long A8[4], A16[4], A32[4];                               \
        _Pragma("unroll")                                                       \
        for (int p = 0; p < 4; p++) { A8[p] = 0ULL; A16[p] = 0ULL; A32[p] = 0ULL; } \
        _Pragma("unroll")                                                       \
        for (int j = 0; j < 32; j++) {                                          \
            unsigned long long w2 = wb[j];                                      \
            _Pragma("unroll")                                                   \
            for (int p = 0; p < 4; p++) FMA2(A32[p], xp[(p << 1) + j], w2, A32[p]); \
        }                                                                       \
        _Pragma("unroll")                                                       \
        for (int j = 0; j < 16; j++) {                                          \
            unsigned long long w2 = wb[32 + j];                                 \
            _Pragma("unroll")                                                   \
            for (int p = 0; p < 4; p++) FMA2(A16[p], xp[16 + (p << 1) + j], w2, A16[p]); \
        }                                                                       \
        _Pragma("unroll")                                                       \
        for (int j = 0; j < 8; j++) {                                           \
            unsigned long long w2 = wb[48 + j];                                 \
            _Pragma("unroll")                                                   \
            for (int p = 0; p < 4; p++) FMA2(A8[p], xp[24 + (p << 1) + j], w2, A8[p]); \
        }                                                                       \
        unsigned long long* u64 = reinterpret_cast<unsigned long long*>(        \
            &UB(((T) & 1), 0, 0, 0));                                           \
        _Pragma("unroll")                                                       \
        for (int p = 0; p < 4; p++) {                                           \
            int c = (tx << 2) + p;                                              \
            u64[(0 * 32 + lane) * (TS / 2) + c] = A8[p];                        \
            u64[(1 * 32 + lane) * (TS / 2) + c] = A16[p];                       \
            u64[(2 * 32 + lane) * (TS / 2) + c] = A32[p];                       \
        }                                                                       \
    } while (0)

    if (wid >= 1) CONV_TILE(0);

    float v0 = 0.f, v1 = 0.f, v2 = 0.f;

#pragma unroll 1
    for (int ti = 0; ti < ntiles; ti++) {
        const int cur = ti & 1, nxt = cur ^ 1;

        // stage x(ti+2); keep one group in flight so x(ti+1) is complete
        if (wid >= 1 && ti + 2 < ntiles) {
            int T = ti + 2;
#pragma unroll
            for (int i = 0; i < 2; i++) {
                int p = ct + (i << 7);
                int row = p >> 3, f4 = p & 7;
                CP_ASYNC16(smem_u32(&XS(T & 3, row, f4 << 2)),
                           x + (size_t)(b0 + row) * TLEN + t_begin + T * TILE + (f4 << 2));
            }
            CP_COMMIT();
            asm volatile("cp.async.wait_group 1;");
        } else {
            asm volatile("cp.async.wait_group 0;");
        }
        __syncthreads();   // x(ti+1) visible; ub[cur]=u(ti) visible; sb[nxt]=s(ti-1) visible

        if (wid == 0) {
            // ---- LIF tile ti ----
            const bool emit = (ti >= wu_tiles);
#pragma unroll
            for (int t4 = 0; t4 < 8; t4++) {
                float4 c0 = *reinterpret_cast<const float4*>(&UB(cur, 0, lane, t4 << 2));
                float4 c1 = *reinterpret_cast<const float4*>(&UB(cur, 1, lane, t4 << 2));
                float4 c2 = *reinterpret_cast<const float4*>(&UB(cur, 2, lane, t4 << 2));
                float4 o0, o1, o2;
                lif_step_s(c0.x, c1.x, c2.x, v0, v1, v2, o0.x, o1.x, o2.x);
                lif_step_s(c0.y, c1.y, c2.y, v0, v1, v2, o0.y, o1.y, o2.y);
                lif_step_s(c0.z, c1.z, c2.z, v0, v1, v2, o0.z, o1.z, o2.z);
                lif_step_s(c0.w, c1.w, c2.w, v0, v1, v2, o0.w, o1.w, o2.w);
                if (emit) {
                    *reinterpret_cast<float4*>(&SB(cur, 0, lane, t4 << 2)) = o0;
                    *reinterpret_cast<float4*>(&SB(cur, 1, lane, t4 << 2)) = o1;
                    *reinterpret_cast<float4*>(&SB(cur, 2, lane, t4 << 2)) = o2;
                }
            }
        } else {
            // ---- store u(ti) ----
            if (ti >= wu_tiles) {
                int tt = t_begin + ti * TILE;
#pragma unroll
                for (int i = 0; i < 6; i++) {
                    int p = ct + (i << 7);
                    int k = p >> 8, row = (p >> 3) & 31, f4 = p & 7;
                    float4 o = *reinterpret_cast<const float4*>(&UB(cur, k, row, f4 << 2));
                    *reinterpret_cast<float4*>(
                        uo + ((size_t)(b0 + row) * 3 + k) * TLEN + tt + (f4 << 2)) = o;
                }
            }
            // ---- conv(ti+1) ----
            if (ti + 1 < ntiles) CONV_TILE(ti + 1);
            // ---- store s(ti-1) ----
            if (ti - 1 >= wu_tiles) {
                int tt = t_begin + (ti - 1) * TILE;
#pragma unroll
                for (int i = 0; i < 6; i++) {
                    int p = ct + (i << 7);
                    int k = p >> 8, row = (p >> 3) & 31, f4 = p & 7;
                    float4 o = *reinterpret_cast<const float4*>(&SB(nxt, k, row, f4 << 2));
                    *reinterpret_cast<float4*>(
                        so + ((size_t)(b0 + row) * 3 + k) * TLEN + tt + (f4 << 2)) = o;
                }
            }
        }
    }

    // epilogue: store s(ntiles-1)
    __syncthreads();
    if (wid >= 1) {
        const int lt = ntiles - 1;
        int tt = t_begin + lt * TILE;
#pragma unroll
        for (int i = 0; i < 6; i++) {
            int p = ct + (i << 7);
            int k = p >> 8, row = (p >> 3) & 31, f4 = p & 7;
            float4 o = *reinterpret_cast<const float4*>(&SB(lt & 1, k, row, f4 << 2));
            *reinterpret_cast<float4*>(
                so + ((size_t)(b0 + row) * 3 + k) * TLEN + tt + (f4 << 2)) = o;
        }
    }
#undef CONV_TILE
}

// ---------------------------------------------------------------------------
extern "C" void kernel_launch(void* const* d_in, const int* in_sizes, int n_in,
                              void* d_out, int out_size)
{
    const float* x   = (const float*)d_in[0];
    const float* w8  = (const float*)d_in[1];
    const float* w16 = (const float*)d_in[2];
    const float* w32 = (const float*)d_in[3];

    float* u = (float*)d_out;
    float* s = u + (size_t)BATCH * 3 * TLEN;

    const int SMEM = (112 + 4 * 32 * TS + 2 * (2 * 3 * 32 * TS)) * 4;  // 74176 B
    static bool attr_set = false;
    if (!attr_set) {
        cudaFuncSetAttribute(fused_kernel,
            cudaFuncAttributeMaxDynamicSharedMemorySize, SMEM);
        attr_set = true;
    }

    fused_kernel<<<dim3(BATCH / ROWS_PB, NSEG), 160, SMEM>>>(x, w8, w16, w32, u, s);
}